// round 5
// baseline (speedup 1.0000x reference)
#include <cuda_runtime.h>
#include <math.h>

// ---------------------------------------------------------------------------
// ImageSectionRNNCell — B=64, image 512x512x3, grid 16x16, U=256
// out layout: h_new[64*256] | c_new[64*256] | next_section[64*3]
//
// Single persistent kernel, 128 blocks x 256 threads (all co-resident on the
// 148-SM GB300), stages separated by hierarchical gmem barriers:
//   front (interp+conv1+conv2) -> dense -> lstm -> nsc1 -> nsc2
// ---------------------------------------------------------------------------

#define B 64
#define U 256
#define IMGH 512
#define IMGW 512
#define NB 128
#define NT 256

__device__ float g_xs[B * 432];   // conv2 output (flattened dense input)
__device__ float g_y [B * U];     // dense output (LSTM input x)
__device__ float g_ns[B * U];     // nsc hidden

// ---- grid barrier state (zero-initialized; self-resetting, gen monotonic) --
__device__ unsigned g_leaf[4][8][32];   // [stage][leaf][pad to 128B]
__device__ unsigned g_root[4];
__device__ unsigned g_gen[4];

__device__ __forceinline__ float sigmoidf_(float x) {
    return 1.0f / (1.0f + __expf(-x));
}

// Hierarchical grid barrier: 128 blocks -> 8 leaves of 16 -> root -> gen bump.
__device__ __forceinline__ void gridbar(int s) {
    __syncthreads();
    if (threadIdx.x == 0) {
        __threadfence();                               // release data
        volatile unsigned* genp = &g_gen[s];
        const unsigned gen0 = *genp;                   // read BEFORE arriving
        const int leaf = blockIdx.x >> 4;
        const unsigned old = atomicAdd(&g_leaf[s][leaf][0], 1);
        if (old == 15) {                               // leaf-last
            g_leaf[s][leaf][0] = 0;                    // reset for next launch
            const unsigned r = atomicAdd(&g_root[s], 1);
            if (r == 7) {                              // global-last
                g_root[s] = 0;
                __threadfence();
                atomicAdd(&g_gen[s], 1);
            }
        }
        while (*genp == gen0) __nanosleep(32);
        __threadfence();                               // acquire data
    }
    __syncthreads();
}

// ---- shared memory union ---------------------------------------------------
struct SFront { float sec[16 * 16 * 3]; float c1o[14 * 14 * 3]; };
struct SDense { float axs[64][148]; float wts[2][144]; float red[256]; };
struct SLstm  { float act[64][132]; float wt[8][132]; float zs[64][8]; };
struct SNsc1  { float axs[64][132]; float wts[2][128]; float red[256]; };
struct SNsc2  { float ns[256]; };

#define SMEM_BYTES 40080

__global__ __launch_bounds__(NT, 1)
void fused_cell(const float* __restrict__ image,
                const float* __restrict__ section,
                const float* __restrict__ c1k, const float* __restrict__ c1b,
                const float* __restrict__ c2k, const float* __restrict__ c2b,
                const float* __restrict__ dw,  const float* __restrict__ db,
                const float* __restrict__ h0,  const float* __restrict__ c0in,
                const float* __restrict__ lk,  const float* __restrict__ lrk,
                const float* __restrict__ lb,
                const float* __restrict__ w1,  const float* __restrict__ b1,
                const float* __restrict__ w2,  const float* __restrict__ b2v,
                float* __restrict__ out)
{
    __shared__ __align__(16) char smem_raw[SMEM_BYTES];
    const int t = threadIdx.x;

    // =======================================================================
    // Stage 0: front — blocks 0..63, one per batch item
    // =======================================================================
    if (blockIdx.x < B) {
        SFront& S = *(SFront*)smem_raw;
        const int b = blockIdx.x;

        // interpolate: thread t -> grid point (i, j)
        {
            const float s0 = section[b * 3 + 0];
            const float s1 = section[b * 3 + 1];
            const float ee = section[b * 3 + 2];
            const int i = t >> 4;
            const int j = t & 15;
            const float p0 = s0 + (float)i * (1.0f / 15.0f) * ee;
            const float p1 = s1 + (float)j * (1.0f / 15.0f) * ee;
            float fy = fminf(fmaxf(p0 * (float)(IMGH - 1), 0.0f), (float)(IMGH - 1));
            float fx = fminf(fmaxf(p1 * (float)(IMGW - 1), 0.0f), (float)(IMGW - 1));
            int y0 = (int)floorf(fy);
            int x0 = (int)floorf(fx);
            int y1 = min(y0 + 1, IMGH - 1);
            int x1 = min(x0 + 1, IMGW - 1);
            float wy = fy - (float)y0;
            float wx = fx - (float)x0;
            const float* img = image + (size_t)b * IMGH * IMGW * 3;
            const float* p00 = img + ((size_t)y0 * IMGW + x0) * 3;
            const float* p01 = img + ((size_t)y0 * IMGW + x1) * 3;
            const float* p10 = img + ((size_t)y1 * IMGW + x0) * 3;
            const float* p11 = img + ((size_t)y1 * IMGW + x1) * 3;
            #pragma unroll
            for (int c = 0; c < 3; c++) {
                float top = p00[c] * (1.0f - wx) + p01[c] * wx;
                float bot = p10[c] * (1.0f - wx) + p11[c] * wx;
                S.sec[(i * 16 + j) * 3 + c] = top * (1.0f - wy) + bot * wy;
            }
        }
        __syncthreads();

        // conv1: (16,16,3) -> (14,14,3), relu
        if (t < 196) {
            const int oh = t / 14;
            const int ow = t - oh * 14;
            float a0 = c1b[0], a1 = c1b[1], a2 = c1b[2];
            #pragma unroll
            for (int kh = 0; kh < 3; kh++)
                #pragma unroll
                for (int kw = 0; kw < 3; kw++) {
                    const float* s = &S.sec[((oh + kh) * 16 + (ow + kw)) * 3];
                    const float* w = &c1k[(kh * 3 + kw) * 9];
                    #pragma unroll
                    for (int ic = 0; ic < 3; ic++) {
                        const float sv = s[ic];
                        a0 += sv * w[ic * 3 + 0];
                        a1 += sv * w[ic * 3 + 1];
                        a2 += sv * w[ic * 3 + 2];
                    }
                }
            S.c1o[t * 3 + 0] = fmaxf(a0, 0.0f);
            S.c1o[t * 3 + 1] = fmaxf(a1, 0.0f);
            S.c1o[t * 3 + 2] = fmaxf(a2, 0.0f);
        }
        __syncthreads();

        // conv2: (14,14,3) -> (12,12,3), relu -> g_xs
        if (t < 144) {
            const int oh = t / 12;
            const int ow = t - oh * 12;
            float a0 = c2b[0], a1 = c2b[1], a2 = c2b[2];
            #pragma unroll
            for (int kh = 0; kh < 3; kh++)
                #pragma unroll
                for (int kw = 0; kw < 3; kw++) {
                    const float* s = &S.c1o[((oh + kh) * 14 + (ow + kw)) * 3];
                    const float* w = &c2k[(kh * 3 + kw) * 9];
                    #pragma unroll
                    for (int ic = 0; ic < 3; ic++) {
                        const float sv = s[ic];
                        a0 += sv * w[ic * 3 + 0];
                        a1 += sv * w[ic * 3 + 1];
                        a2 += sv * w[ic * 3 + 2];
                    }
                }
            float* dst = g_xs + b * 432 + t * 3;
            dst[0] = fmaxf(a0, 0.0f);
            dst[1] = fmaxf(a1, 0.0f);
            dst[2] = fmaxf(a2, 0.0f);
        }
    }
    gridbar(0);

    // =======================================================================
    // Stage 1: dense y = relu(xs @ dw + db). Block j owns units 2j, 2j+1.
    // thread = (b = t&63, d = (t>>6)&1, h = t>>7) ; split-k halves.
    // =======================================================================
    {
        SDense& S = *(SDense*)smem_raw;
        const int j = blockIdx.x;
        const int b = t & 63;
        const int d = (t >> 6) & 1;
        const int h = t >> 7;
        float acc0 = 0.f, acc1 = 0.f, acc2 = 0.f, acc3 = 0.f;

        for (int ch = 0; ch < 3; ch++) {
            const int k0 = ch * 144;
            for (int i = t; i < 64 * 36; i += NT) {
                const int row = i / 36;
                const int c4  = i - row * 36;
                const float4 v = __ldcg((const float4*)(g_xs + row * 432 + k0 + c4 * 4));
                *(float4*)&S.axs[row][c4 * 4] = v;
            }
            if (t < 144) {
                const float2 w = __ldcg((const float2*)(dw + (size_t)(k0 + t) * U + 2 * j));
                S.wts[0][t] = w.x;
                S.wts[1][t] = w.y;
            }
            __syncthreads();

            const float* xr = &S.axs[b][h * 72];
            const float* wr = &S.wts[d][h * 72];
            #pragma unroll
            for (int q = 0; q < 18; q += 2) {
                const float4 x0 = *(const float4*)(xr + q * 4);
                const float4 w0 = *(const float4*)(wr + q * 4);
                acc0 += x0.x * w0.x + x0.y * w0.y;
                acc1 += x0.z * w0.z + x0.w * w0.w;
                const float4 x1 = *(const float4*)(xr + q * 4 + 4);
                const float4 w1v = *(const float4*)(wr + q * 4 + 4);
                acc2 += x1.x * w1v.x + x1.y * w1v.y;
                acc3 += x1.z * w1v.z + x1.w * w1v.w;
            }
            __syncthreads();
        }

        S.red[t] = acc0 + acc1 + acc2 + acc3;
        __syncthreads();
        if (t < 128) {
            const int b2 = t & 63;
            const int d2 = t >> 6;
            const int u  = 2 * j + d2;
            g_y[b2 * U + u] = fmaxf(S.red[t] + S.red[t + 128] + db[u], 0.0f);
        }
    }
    gridbar(1);

    // =======================================================================
    // Stage 2: LSTM. Block j owns units {2j, 2j+1} -> 8 z-cols x 64 batches.
    // thread = (cp = t&3, bp = t>>2). K = 512 in 4 chunks of 128.
    // =======================================================================
    {
        SLstm& S = *(SLstm*)smem_raw;
        const int j  = blockIdx.x;
        const int cp = t & 3;
        const int bp = t >> 2;   // 0..63
        float a00 = 0.f, a01 = 0.f, a10 = 0.f, a11 = 0.f;

        for (int ch = 0; ch < 4; ch++) {
            const bool fromY = (ch < 2);
            for (int i = t; i < 64 * 32; i += NT) {
                const int row = i >> 5;
                const int c4  = i & 31;
                float4 v;
                if (fromY) v = __ldcg((const float4*)(g_y + row * U + ch * 128 + c4 * 4));
                else       v = *(const float4*)(h0 + row * U + (ch - 2) * 128 + c4 * 4);
                *(float4*)&S.act[row][c4 * 4] = v;
            }
            if (t < 128) {
                const float* wsrc = fromY ? lk : lrk;
                const int krow = (fromY ? ch : (ch - 2)) * 128 + t;
                const float* wr = wsrc + (size_t)krow * (4 * U) + 2 * j;
                #pragma unroll
                for (int g = 0; g < 4; g++) {
                    const float2 wv = __ldcg((const float2*)(wr + g * U));
                    S.wt[2 * g + 0][t] = wv.x;
                    S.wt[2 * g + 1][t] = wv.y;
                }
            }
            __syncthreads();

            const float* xr  = &S.act[bp][0];
            const float* w0r = &S.wt[2 * cp][0];
            const float* w1r = &S.wt[2 * cp + 1][0];
            #pragma unroll
            for (int kk = 0; kk < 128; kk += 8) {
                const float4 x0 = *(const float4*)(xr + kk);
                const float4 u0 = *(const float4*)(w0r + kk);
                const float4 v0 = *(const float4*)(w1r + kk);
                a00 += x0.x * u0.x + x0.y * u0.y + x0.z * u0.z + x0.w * u0.w;
                a10 += x0.x * v0.x + x0.y * v0.y + x0.z * v0.z + x0.w * v0.w;
                const float4 x1 = *(const float4*)(xr + kk + 4);
                const float4 u1 = *(const float4*)(w0r + kk + 4);
                const float4 v1 = *(const float4*)(w1r + kk + 4);
                a01 += x1.x * u1.x + x1.y * u1.y + x1.z * u1.z + x1.w * u1.w;
                a11 += x1.x * v1.x + x1.y * v1.y + x1.z * v1.z + x1.w * v1.w;
            }
            __syncthreads();
        }

        S.zs[bp][2 * cp + 0] = a00 + a01 + lb[cp * U + 2 * j + 0];
        S.zs[bp][2 * cp + 1] = a10 + a11 + lb[cp * U + 2 * j + 1];
        __syncthreads();

        if (t < 128) {
            const int bb = t >> 1;
            const int d  = t & 1;
            const int u  = 2 * j + d;
            const float iz = S.zs[bb][0 + d];
            const float fz = S.zs[bb][2 + d];
            const float gz = S.zs[bb][4 + d];
            const float oz = S.zs[bb][6 + d];
            const float cprev = c0in[bb * U + u];
            const float cn = sigmoidf_(fz) * cprev + sigmoidf_(iz) * tanhf(gz);
            const float hn = sigmoidf_(oz) * tanhf(cn);
            out[bb * U + u]         = hn;
            out[B * U + bb * U + u] = cn;
        }
    }
    gridbar(2);

    // =======================================================================
    // Stage 3: nsc1 ns = relu(h_new @ W1 + b1). Block j owns units 2j, 2j+1.
    // thread = (b, d, h) split-k (h picks 64-wide half of each 128 chunk).
    // =======================================================================
    {
        SNsc1& S = *(SNsc1*)smem_raw;
        const int j = blockIdx.x;
        const int b = t & 63;
        const int d = (t >> 6) & 1;
        const int h = t >> 7;
        float acc0 = 0.f, acc1 = 0.f;

        for (int ch = 0; ch < 2; ch++) {
            for (int i = t; i < 64 * 32; i += NT) {
                const int row = i >> 5;
                const int c4  = i & 31;
                const float4 v = __ldcg((const float4*)(out + row * U + ch * 128 + c4 * 4));
                *(float4*)&S.axs[row][c4 * 4] = v;
            }
            if (t < 128) {
                const float2 w = __ldcg((const float2*)(w1 + (size_t)(ch * 128 + t) * U + 2 * j));
                S.wts[0][t] = w.x;
                S.wts[1][t] = w.y;
            }
            __syncthreads();

            const float* xr = &S.axs[b][h * 64];
            const float* wr = &S.wts[d][h * 64];
            #pragma unroll
            for (int kk = 0; kk < 64; kk += 8) {
                const float4 x0 = *(const float4*)(xr + kk);
                const float4 w0 = *(const float4*)(wr + kk);
                acc0 += x0.x * w0.x + x0.y * w0.y + x0.z * w0.z + x0.w * w0.w;
                const float4 x1 = *(const float4*)(xr + kk + 4);
                const float4 w1v = *(const float4*)(wr + kk + 4);
                acc1 += x1.x * w1v.x + x1.y * w1v.y + x1.z * w1v.z + x1.w * w1v.w;
            }
            __syncthreads();
        }

        S.red[t] = acc0 + acc1;
        __syncthreads();
        if (t < 128) {
            const int b2 = t & 63;
            const int d2 = t >> 6;
            const int u  = 2 * j + d2;
            g_ns[b2 * U + u] = fmaxf(S.red[t] + S.red[t + 128] + b1[u], 0.0f);
        }
    }
    gridbar(3);

    // =======================================================================
    // Stage 4: nsc2 next_section = sigmoid(ns @ W2 + b2). Blocks 0..63.
    // =======================================================================
    if (blockIdx.x < B) {
        SNsc2& S = *(SNsc2*)smem_raw;
        const int b = blockIdx.x;
        S.ns[t] = __ldcg(g_ns + b * U + t);
        __syncthreads();
        if (t < 96) {
            const int g = t >> 5;
            const int l = t & 31;
            float s = 0.0f;
            #pragma unroll
            for (int k = l; k < U; k += 32)
                s += S.ns[k] * w2[k * 3 + g];
            #pragma unroll
            for (int o = 16; o > 0; o >>= 1)
                s += __shfl_down_sync(0xffffffffu, s, o);
            if (l == 0)
                out[2 * B * U + b * 3 + g] = sigmoidf_(s + b2v[g]);
        }
    }
}

// ===========================================================================
extern "C" void kernel_launch(void* const* d_in, const int* in_sizes, int n_in,
                              void* d_out, int out_size)
{
    const float* image   = (const float*)d_in[0];
    const float* section = (const float*)d_in[1];
    const float* h0      = (const float*)d_in[2];
    const float* c0      = (const float*)d_in[3];
    const float* conv1_k = (const float*)d_in[4];
    const float* conv1_b = (const float*)d_in[5];
    const float* conv2_k = (const float*)d_in[6];
    const float* conv2_b = (const float*)d_in[7];
    const float* dense_w = (const float*)d_in[8];
    const float* dense_b = (const float*)d_in[9];
    const float* lstm_k  = (const float*)d_in[10];
    const float* lstm_rk = (const float*)d_in[11];
    const float* lstm_b  = (const float*)d_in[12];
    const float* nsc_w1  = (const float*)d_in[13];
    const float* nsc_b1  = (const float*)d_in[14];
    const float* nsc_w2  = (const float*)d_in[15];
    const float* nsc_b2  = (const float*)d_in[16];
    float* out = (float*)d_out;

    fused_cell<<<NB, NT>>>(image, section,
                           conv1_k, conv1_b, conv2_k, conv2_b,
                           dense_w, dense_b,
                           h0, c0, lstm_k, lstm_rk, lstm_b,
                           nsc_w1, nsc_b1, nsc_w2, nsc_b2,
                           out);
}

// round 7
// speedup vs baseline: 1.9658x; 1.9658x over previous
#include <cuda_runtime.h>
#include <math.h>

// ---------------------------------------------------------------------------
// ImageSectionRNNCell — B=64, image 512x512x3, grid 16x16, U=256
// out layout: h_new[64*256] | c_new[64*256] | next_section[64*3]
//
// 6 kernels, every GEMM 2D-tiled (unit-tile x k-tile) to stay under the
// per-SM LDG issue floor (1.82 cyc/LDG). Partial sums combined via
// atomicAdd into bias-initialized accumulators, or per-ktile buffers.
// ---------------------------------------------------------------------------

#define B 64
#define U 256
#define IMGH 512
#define IMGW 512

__device__ float g_xs[B * 432];        // conv2 output (dense input)
__device__ float g_y [B * U];          // dense pre-act accumulator (bias-init)
__device__ float g_zp[4][B][4 * U];    // LSTM partials per k-tile
__device__ float g_ns[B * U];          // nsc1 pre-act accumulator (bias-init)

__device__ __forceinline__ float sigmoidf_(float x) {
    return 1.0f / (1.0f + __expf(-x));
}

// ===========================================================================
// K1: bias-init g_y/g_ns + interpolate + conv1 + conv2 -> g_xs
// 64 blocks (one per batch) x 256 threads
// ===========================================================================
__global__ __launch_bounds__(256, 4)
void k1_front(const float* __restrict__ image,
              const float* __restrict__ section,
              const float* __restrict__ c1k, const float* __restrict__ c1b,
              const float* __restrict__ c2k, const float* __restrict__ c2b,
              const float* __restrict__ db,  const float* __restrict__ b1)
{
    const int b = blockIdx.x;
    const int t = threadIdx.x;

    // bias-init the two atomic accumulators (64 blocks x 256 thr = exact cover)
    g_y [b * U + t] = db[t];
    g_ns[b * U + t] = b1[t];

    __shared__ float sec[16 * 16 * 3];
    __shared__ float c1o[14 * 14 * 3];

    // ---- interpolate: thread t -> grid point (i, j) ----
    {
        const float s0 = section[b * 3 + 0];
        const float s1 = section[b * 3 + 1];
        const float ee = section[b * 3 + 2];
        const int i = t >> 4;
        const int j = t & 15;
        const float p0 = s0 + (float)i * (1.0f / 15.0f) * ee;
        const float p1 = s1 + (float)j * (1.0f / 15.0f) * ee;
        float fy = fminf(fmaxf(p0 * (float)(IMGH - 1), 0.0f), (float)(IMGH - 1));
        float fx = fminf(fmaxf(p1 * (float)(IMGW - 1), 0.0f), (float)(IMGW - 1));
        int y0 = (int)floorf(fy);
        int x0 = (int)floorf(fx);
        int y1 = min(y0 + 1, IMGH - 1);
        int x1 = min(x0 + 1, IMGW - 1);
        float wy = fy - (float)y0;
        float wx = fx - (float)x0;
        const float* img = image + (size_t)b * IMGH * IMGW * 3;
        const float* p00 = img + ((size_t)y0 * IMGW + x0) * 3;
        const float* p01 = img + ((size_t)y0 * IMGW + x1) * 3;
        const float* p10 = img + ((size_t)y1 * IMGW + x0) * 3;
        const float* p11 = img + ((size_t)y1 * IMGW + x1) * 3;
        #pragma unroll
        for (int c = 0; c < 3; c++) {
            float top = p00[c] * (1.0f - wx) + p01[c] * wx;
            float bot = p10[c] * (1.0f - wx) + p11[c] * wx;
            sec[(i * 16 + j) * 3 + c] = top * (1.0f - wy) + bot * wy;
        }
    }
    __syncthreads();

    // ---- conv1: (16,16,3) -> (14,14,3), relu ----
    if (t < 196) {
        const int oh = t / 14;
        const int ow = t - oh * 14;
        float a0 = c1b[0], a1 = c1b[1], a2 = c1b[2];
        #pragma unroll
        for (int kh = 0; kh < 3; kh++)
            #pragma unroll
            for (int kw = 0; kw < 3; kw++) {
                const float* s = &sec[((oh + kh) * 16 + (ow + kw)) * 3];
                const float* w = &c1k[(kh * 3 + kw) * 9];
                #pragma unroll
                for (int ic = 0; ic < 3; ic++) {
                    const float sv = s[ic];
                    a0 += sv * w[ic * 3 + 0];
                    a1 += sv * w[ic * 3 + 1];
                    a2 += sv * w[ic * 3 + 2];
                }
            }
        c1o[t * 3 + 0] = fmaxf(a0, 0.0f);
        c1o[t * 3 + 1] = fmaxf(a1, 0.0f);
        c1o[t * 3 + 2] = fmaxf(a2, 0.0f);
    }
    __syncthreads();

    // ---- conv2: (14,14,3) -> (12,12,3), relu -> g_xs ----
    if (t < 144) {
        const int oh = t / 12;
        const int ow = t - oh * 12;
        float a0 = c2b[0], a1 = c2b[1], a2 = c2b[2];
        #pragma unroll
        for (int kh = 0; kh < 3; kh++)
            #pragma unroll
            for (int kw = 0; kw < 3; kw++) {
                const float* s = &c1o[((oh + kh) * 14 + (ow + kw)) * 3];
                const float* w = &c2k[(kh * 3 + kw) * 9];
                #pragma unroll
                for (int ic = 0; ic < 3; ic++) {
                    const float sv = s[ic];
                    a0 += sv * w[ic * 3 + 0];
                    a1 += sv * w[ic * 3 + 1];
                    a2 += sv * w[ic * 3 + 2];
                }
            }
        float* dst = g_xs + b * 432 + t * 3;
        dst[0] = fmaxf(a0, 0.0f);
        dst[1] = fmaxf(a1, 0.0f);
        dst[2] = fmaxf(a2, 0.0f);
    }
}

// ===========================================================================
// K2: dense partial. 128 blocks = 32 unit-tiles (8 units) x 4 k-tiles (108).
// atomicAdd into g_y (bias pre-initialized). ReLU applied by consumer.
// ===========================================================================
__global__ __launch_bounds__(256, 1)
void k2_dense(const float* __restrict__ dw)
{
    const int ut = blockIdx.x & 31;
    const int kt = blockIdx.x >> 5;
    const int t  = threadIdx.x;
    const int k0 = kt * 108;

    __shared__ float axs[64][112];   // act k-slice [batch][108]
    __shared__ float wts[108][12];   // weight tile [k][8 units]

    for (int i = t; i < 64 * 27; i += 256) {
        const int row = i / 27;
        const int c4  = i - row * 27;
        const float4 v = *(const float4*)(g_xs + row * 432 + k0 + c4 * 4);
        *(float4*)&axs[row][c4 * 4] = v;
    }
    if (t < 216) {
        const int row = t >> 1;
        const int h   = t & 1;
        const float4 w = *(const float4*)(dw + (size_t)(k0 + row) * U + ut * 8 + h * 4);
        *(float4*)&wts[row][h * 4] = w;
    }
    __syncthreads();

    const int u2 = t & 3;        // 2 units: 2*u2, 2*u2+1
    const int bp = t >> 2;       // batch 0..63
    float a0 = 0.f, a1 = 0.f, a2 = 0.f, a3 = 0.f;
    #pragma unroll 2
    for (int k = 0; k < 108; k += 2) {
        const float x0 = axs[bp][k];
        const float x1 = axs[bp][k + 1];
        const float2 w0 = *(const float2*)&wts[k][u2 * 2];
        const float2 w1 = *(const float2*)&wts[k + 1][u2 * 2];
        a0 += x0 * w0.x; a1 += x0 * w0.y;
        a2 += x1 * w1.x; a3 += x1 * w1.y;
    }
    const int u = ut * 8 + u2 * 2;
    atomicAdd(&g_y[bp * U + u],     a0 + a2);
    atomicAdd(&g_y[bp * U + u + 1], a1 + a3);
}

// ===========================================================================
// K3: LSTM partial. 128 blocks = 32 col-tiles (32 z-cols) x 4 k-tiles (128).
// kt<2 : acts = relu(g_y) (dense activation applied here), weights = lstm_k
// kt>=2: acts = h0,                                  weights = lstm_rk
// Partials -> g_zp[kt] (plain stores, no atomics).
// Dynamic smem: act[64][132] + wt[128][36] = 52224 bytes.
// ===========================================================================
__global__ __launch_bounds__(256, 1)
void k3_lstm(const float* __restrict__ h0,
             const float* __restrict__ lk, const float* __restrict__ lrk)
{
    extern __shared__ float dsm[];
    float (*act)[132] = (float(*)[132])dsm;               // 64 x 132
    float (*wt)[36]   = (float(*)[36])(dsm + 64 * 132);   // 128 x 36

    const int ct = blockIdx.x & 31;
    const int kt = blockIdx.x >> 5;
    const int t  = threadIdx.x;

    if (kt < 2) {
        const float* base = g_y + kt * 128;
        for (int i = t; i < 64 * 32; i += 256) {
            const int row = i >> 5;
            const int c4  = i & 31;
            float4 v = *(const float4*)(base + row * U + c4 * 4);
            v.x = fmaxf(v.x, 0.f); v.y = fmaxf(v.y, 0.f);
            v.z = fmaxf(v.z, 0.f); v.w = fmaxf(v.w, 0.f);
            *(float4*)&act[row][c4 * 4] = v;
        }
    } else {
        const float* base = h0 + (kt - 2) * 128;
        for (int i = t; i < 64 * 32; i += 256) {
            const int row = i >> 5;
            const int c4  = i & 31;
            const float4 v = *(const float4*)(base + row * U + c4 * 4);
            *(float4*)&act[row][c4 * 4] = v;
        }
    }
    {
        const float* wsrc = (kt < 2) ? (lk + (size_t)kt * 128 * 1024)
                                     : (lrk + (size_t)(kt - 2) * 128 * 1024);
        for (int i = t; i < 128 * 8; i += 256) {
            const int row = i >> 3;
            const int c4  = i & 7;
            const float4 w = *(const float4*)(wsrc + (size_t)row * 1024 + ct * 32 + c4 * 4);
            *(float4*)&wt[row][c4 * 4] = w;
        }
    }
    __syncthreads();

    const int c4 = t & 7;        // 4 cols: ct*32 + c4*4 ..
    const int bp = t >> 3;       // batches bp, bp+32
    float s00 = 0.f, s01 = 0.f, s02 = 0.f, s03 = 0.f;
    float s10 = 0.f, s11 = 0.f, s12 = 0.f, s13 = 0.f;
    #pragma unroll 4
    for (int k = 0; k < 128; k++) {
        const float a0 = act[bp][k];
        const float a1 = act[bp + 32][k];
        const float4 w = *(const float4*)&wt[k][c4 * 4];
        s00 += a0 * w.x; s01 += a0 * w.y; s02 += a0 * w.z; s03 += a0 * w.w;
        s10 += a1 * w.x; s11 += a1 * w.y; s12 += a1 * w.z; s13 += a1 * w.w;
    }
    const int col = ct * 32 + c4 * 4;
    *(float4*)&g_zp[kt][bp][col]      = make_float4(s00, s01, s02, s03);
    *(float4*)&g_zp[kt][bp + 32][col] = make_float4(s10, s11, s12, s13);
}

// ===========================================================================
// K4: gates. 64 blocks x 256 threads, thread = (batch, unit).
// Sums the 4 k-tile partials, adds bias, applies LSTM nonlinearity,
// writes h_new/c_new into out.
// ===========================================================================
__global__ __launch_bounds__(256, 4)
void k4_gates(const float* __restrict__ c0in, const float* __restrict__ lb,
              float* __restrict__ out)
{
    const int b = blockIdx.x;
    const int u = threadIdx.x;

    float zi = 0.f, zf = 0.f, zg = 0.f, zo = 0.f;
    #pragma unroll
    for (int kt = 0; kt < 4; kt++) {
        const float* p = &g_zp[kt][b][0];
        zi += p[u];
        zf += p[U + u];
        zg += p[2 * U + u];
        zo += p[3 * U + u];
    }
    zi += lb[u];
    zf += lb[U + u];
    zg += lb[2 * U + u];
    zo += lb[3 * U + u];

    const float cprev = c0in[b * U + u];
    const float cn = sigmoidf_(zf) * cprev + sigmoidf_(zi) * tanhf(zg);
    const float hn = sigmoidf_(zo) * tanhf(cn);
    out[b * U + u]         = hn;
    out[B * U + b * U + u] = cn;
}

// ===========================================================================
// K5: nsc1 partial. 64 blocks = 32 unit-tiles (8 units) x 2 k-tiles (128).
// acts = h_new (from out). atomicAdd into g_ns (bias pre-initialized).
// ===========================================================================
__global__ __launch_bounds__(256, 1)
void k5_nsc1(const float* __restrict__ w1, const float* __restrict__ out)
{
    const int ut = blockIdx.x & 31;
    const int kt = blockIdx.x >> 5;
    const int t  = threadIdx.x;

    __shared__ float axs[64][132];
    __shared__ float wts[128][12];

    for (int i = t; i < 64 * 32; i += 256) {
        const int row = i >> 5;
        const int c4  = i & 31;
        const float4 v = *(const float4*)(out + row * U + kt * 128 + c4 * 4);
        *(float4*)&axs[row][c4 * 4] = v;
    }
    {
        const int row = t >> 1;
        const int h   = t & 1;
        const float4 w = *(const float4*)(w1 + (size_t)(kt * 128 + row) * U + ut * 8 + h * 4);
        *(float4*)&wts[row][h * 4] = w;
    }
    __syncthreads();

    const int u2 = t & 3;
    const int bp = t >> 2;
    float a0 = 0.f, a1 = 0.f, a2 = 0.f, a3 = 0.f;
    #pragma unroll 4
    for (int k = 0; k < 128; k += 2) {
        const float x0 = axs[bp][k];
        const float x1 = axs[bp][k + 1];
        const float2 w0 = *(const float2*)&wts[k][u2 * 2];
        const float2 w1v = *(const float2*)&wts[k + 1][u2 * 2];
        a0 += x0 * w0.x;  a1 += x0 * w0.y;
        a2 += x1 * w1v.x; a3 += x1 * w1v.y;
    }
    const int u = ut * 8 + u2 * 2;
    atomicAdd(&g_ns[bp * U + u],     a0 + a2);
    atomicAdd(&g_ns[bp * U + u + 1], a1 + a3);
}

// ===========================================================================
// K6: nsc2. next_section = sigmoid(relu(g_ns) @ W2 + b2). 64 blocks x 96.
// ===========================================================================
__global__ __launch_bounds__(96, 8)
void k6_nsc2(const float* __restrict__ w2, const float* __restrict__ b2,
             float* __restrict__ out)
{
    const int b = blockIdx.x;
    const int t = threadIdx.x;
    const int g = t >> 5;
    const int l = t & 31;

    const float* ns = g_ns + b * U;
    float s = 0.0f;
    #pragma unroll
    for (int k = l; k < U; k += 32)
        s += fmaxf(ns[k], 0.0f) * w2[k * 3 + g];
    #pragma unroll
    for (int o = 16; o > 0; o >>= 1)
        s += __shfl_down_sync(0xffffffffu, s, o);
    if (l == 0)
        out[2 * B * U + b * 3 + g] = sigmoidf_(s + b2[g]);
}

// ===========================================================================
extern "C" void kernel_launch(void* const* d_in, const int* in_sizes, int n_in,
                              void* d_out, int out_size)
{
    const float* image   = (const float*)d_in[0];
    const float* section = (const float*)d_in[1];
    const float* h0      = (const float*)d_in[2];
    const float* c0      = (const float*)d_in[3];
    const float* conv1_k = (const float*)d_in[4];
    const float* conv1_b = (const float*)d_in[5];
    const float* conv2_k = (const float*)d_in[6];
    const float* conv2_b = (const float*)d_in[7];
    const float* dense_w = (const float*)d_in[8];
    const float* dense_b = (const float*)d_in[9];
    const float* lstm_k  = (const float*)d_in[10];
    const float* lstm_rk = (const float*)d_in[11];
    const float* lstm_b  = (const float*)d_in[12];
    const float* nsc_w1  = (const float*)d_in[13];
    const float* nsc_b1  = (const float*)d_in[14];
    const float* nsc_w2  = (const float*)d_in[15];
    const float* nsc_b2  = (const float*)d_in[16];
    float* out = (float*)d_out;

    static int attr_done = 0;
    if (!attr_done) {
        cudaFuncSetAttribute(k3_lstm,
                             cudaFuncAttributeMaxDynamicSharedMemorySize,
                             64 * 1024);
        attr_done = 1;
    }

    k1_front<<<B, 256>>>(image, section, conv1_k, conv1_b,
                         conv2_k, conv2_b, dense_b, nsc_b1);
    k2_dense<<<128, 256>>>(dense_w);
    k3_lstm<<<128, 256, (64 * 132 + 128 * 36) * 4>>>(h0, lstm_k, lstm_rk);
    k4_gates<<<B, 256>>>(c0, lstm_b, out);
    k5_nsc1<<<64, 256>>>(nsc_w1, out);
    k6_nsc2<<<B, 96>>>(nsc_w2, nsc_b2, out);
}